// round 1
// baseline (speedup 1.0000x reference)
#include <cuda_runtime.h>

#define HEADS 16
#define DHEAD 64
#define NSEQ  2048
#define NB    2
#define INNER 1024      // HEADS*DHEAD
#define NQKV  3072      // 3*INNER
#define MTOK  4096      // NB*NSEQ
#define KDIM  1024

// ---------------- scratch (device globals; no runtime allocation) ----------------
__device__ float g_q[NB * HEADS * NSEQ * DHEAD];    // [bh][n][d], pre-scaled by SCALE
__device__ float g_k[NB * HEADS * NSEQ * DHEAD];
__device__ float g_v[NB * HEADS * NSEQ * DHEAD];
__device__ float g_attn[MTOK * INNER];              // [b*n][h*d]

// =================================================================================
// GEMM 1: qkv = x @ w_qkv   (M=4096, N=3072, K=1024)
// Epilogue scatters into g_q/g_k/g_v with [b,h,n,d] layout; q scaled by 0.125.
// =================================================================================
__global__ __launch_bounds__(256) void qkv_gemm_kernel(const float* __restrict__ A,
                                                       const float* __restrict__ B)
{
    __shared__ float As[8][128];   // [k][m] transposed
    __shared__ float Bs[8][128];   // [k][n]

    const int tid  = threadIdx.x;
    const int ty   = tid >> 4;          // 0..15  -> rows ty*8..+7
    const int tx   = tid & 15;          // 0..15  -> cols tx*8..+7
    const int arow = tid >> 1;          // 0..127
    const int ac4  = (tid & 1) << 2;    // 0 or 4
    const int brow = tid >> 5;          // 0..7
    const int bc4  = (tid & 31) << 2;   // 0..124

    const float* Ap = A + (blockIdx.y * 128 + arow) * KDIM + ac4;
    const float* Bp = B + brow * NQKV + blockIdx.x * 128 + bc4;

    float acc[8][8];
    #pragma unroll
    for (int i = 0; i < 8; i++)
        #pragma unroll
        for (int j = 0; j < 8; j++) acc[i][j] = 0.0f;

    for (int k0 = 0; k0 < KDIM; k0 += 8) {
        float4 av = *(const float4*)(Ap + k0);
        float4 bv = *(const float4*)(Bp + (size_t)k0 * NQKV);
        As[ac4 + 0][arow] = av.x;
        As[ac4 + 1][arow] = av.y;
        As[ac4 + 2][arow] = av.z;
        As[ac4 + 3][arow] = av.w;
        *(float4*)&Bs[brow][bc4] = bv;
        __syncthreads();

        #pragma unroll
        for (int kk = 0; kk < 8; kk++) {
            float a[8], b[8];
            *(float4*)&a[0] = *(const float4*)&As[kk][ty * 8];
            *(float4*)&a[4] = *(const float4*)&As[kk][ty * 8 + 4];
            *(float4*)&b[0] = *(const float4*)&Bs[kk][tx * 8];
            *(float4*)&b[4] = *(const float4*)&Bs[kk][tx * 8 + 4];
            #pragma unroll
            for (int i = 0; i < 8; i++)
                #pragma unroll
                for (int j = 0; j < 8; j++)
                    acc[i][j] += a[i] * b[j];
        }
        __syncthreads();
    }

    // scatter epilogue: col = s*1024 + h*64 + d  ->  dst[((b*16+h)*2048+n)*64 + d]
    const int col0 = blockIdx.x * 128 + tx * 8;   // 8-col chunk never crosses h or s boundary
    const int s    = col0 >> 10;
    const int h    = (col0 >> 6) & 15;
    const int d0   = col0 & 63;
    float* dst = (s == 0) ? g_q : (s == 1) ? g_k : g_v;
    const float mul = (s == 0) ? 0.125f : 1.0f;   // SCALE = 64^-0.5

    #pragma unroll
    for (int i = 0; i < 8; i++) {
        int row = blockIdx.y * 128 + ty * 8 + i;
        int b_  = row >> 11;
        int nn  = row & 2047;
        float* p = dst + (((b_ * HEADS + h) * NSEQ + nn) * DHEAD + d0);
        float4 v0 = make_float4(acc[i][0] * mul, acc[i][1] * mul, acc[i][2] * mul, acc[i][3] * mul);
        float4 v1 = make_float4(acc[i][4] * mul, acc[i][5] * mul, acc[i][6] * mul, acc[i][7] * mul);
        *(float4*)p       = v0;
        *(float4*)(p + 4) = v1;
    }
}

// =================================================================================
// RoPE on g_q and g_k in place. One thread per (d, d+32) pair per (bh, n).
// =================================================================================
__global__ __launch_bounds__(256) void rope_kernel()
{
    int idx = blockIdx.x * blockDim.x + threadIdx.x;  // < 32*2048*32 = 2^21
    int d  = idx & 31;
    int nn = (idx >> 5) & 2047;
    int bh = idx >> 16;

    float theta = __powf(10000.0f, -(float)d * (1.0f / 32.0f));
    float ang = (float)nn * theta;
    float sv, cv;
    sincosf(ang, &sv, &cv);   // precise version: args up to 2047

    int base = (bh * NSEQ + nn) * DHEAD + d;
    {
        float x1 = g_q[base], x2 = g_q[base + 32];
        g_q[base]      = x1 * cv - x2 * sv;
        g_q[base + 32] = x1 * sv + x2 * cv;
    }
    {
        float x1 = g_k[base], x2 = g_k[base + 32];
        g_k[base]      = x1 * cv - x2 * sv;
        g_k[base + 32] = x1 * sv + x2 * cv;
    }
}

// =================================================================================
// Flash attention (fp32): grid (32 q-tiles, 32 bh), 256 threads.
// Tiles: 64 queries x 64 keys, d=64. Thread t owns 4x4 micro-tiles:
//   rgrp = t/16 -> rows rgrp*4..+3, cgrp = t%16 -> cols cgrp*4..+3.
// Row reductions via shfl_xor over the 16 lanes sharing a row group.
// Dynamic smem 64KB: QsT[d][r], KsT[d][j], Vs[j][d], Ps[r][j] (all [64][64]).
// =================================================================================
__global__ __launch_bounds__(256) void attn_kernel()
{
    extern __shared__ float sm[];
    float* QsT = sm;            // [64][64]  (d-major)
    float* KsT = sm + 4096;     // [64][64]  (d-major)
    float* Vs  = sm + 8192;     // [64][64]  (j-major)
    float* Ps  = sm + 12288;    // [64][64]  (r-major)

    const int tid  = threadIdx.x;
    const int qt   = blockIdx.x;
    const int bh   = blockIdx.y;
    const int rgrp = tid >> 4;
    const int cgrp = tid & 15;

    const float* qp = g_q + (size_t)bh * NSEQ * DHEAD;
    const float* kp = g_k + (size_t)bh * NSEQ * DHEAD;
    const float* vp = g_v + (size_t)bh * NSEQ * DHEAD;

    // load Q tile, transposed into QsT[d][r]
    #pragma unroll
    for (int i = 0; i < 4; i++) {
        int f = tid + i * 256;
        int r = f & 63;
        int c4 = (f >> 6) << 2;
        float4 v = *(const float4*)(qp + (qt * 64 + r) * DHEAD + c4);
        QsT[(c4 + 0) * 64 + r] = v.x;
        QsT[(c4 + 1) * 64 + r] = v.y;
        QsT[(c4 + 2) * 64 + r] = v.z;
        QsT[(c4 + 3) * 64 + r] = v.w;
    }

    float o[4][4];
    float m[4], l[4];
    #pragma unroll
    for (int ri = 0; ri < 4; ri++) {
        m[ri] = -1e30f; l[ri] = 0.0f;
        #pragma unroll
        for (int ci = 0; ci < 4; ci++) o[ri][ci] = 0.0f;
    }

    for (int kt = 0; kt < NSEQ / 64; kt++) {
        __syncthreads();   // previous iteration's reads of KsT/Vs complete

        // load K (transposed) and V (natural)
        #pragma unroll
        for (int i = 0; i < 4; i++) {
            int f = tid + i * 256;
            int r = f & 63;
            int c4 = (f >> 6) << 2;
            float4 v = *(const float4*)(kp + (kt * 64 + r) * DHEAD + c4);
            KsT[(c4 + 0) * 64 + r] = v.x;
            KsT[(c4 + 1) * 64 + r] = v.y;
            KsT[(c4 + 2) * 64 + r] = v.z;
            KsT[(c4 + 3) * 64 + r] = v.w;
        }
        #pragma unroll
        for (int i = 0; i < 4; i++) {
            int f = tid + i * 256;
            int r = f >> 4;
            int c4 = (f & 15) << 2;
            *(float4*)&Vs[r * 64 + c4] = *(const float4*)(vp + (kt * 64 + r) * DHEAD + c4);
        }
        __syncthreads();

        // S = Q K^T  (Q already scaled)
        float s[4][4];
        #pragma unroll
        for (int ri = 0; ri < 4; ri++)
            #pragma unroll
            for (int ci = 0; ci < 4; ci++) s[ri][ci] = 0.0f;

        #pragma unroll 8
        for (int kd = 0; kd < 64; kd++) {
            float4 aq = *(const float4*)&QsT[kd * 64 + rgrp * 4];
            float4 bk = *(const float4*)&KsT[kd * 64 + cgrp * 4];
            s[0][0] += aq.x * bk.x; s[0][1] += aq.x * bk.y; s[0][2] += aq.x * bk.z; s[0][3] += aq.x * bk.w;
            s[1][0] += aq.y * bk.x; s[1][1] += aq.y * bk.y; s[1][2] += aq.y * bk.z; s[1][3] += aq.y * bk.w;
            s[2][0] += aq.z * bk.x; s[2][1] += aq.z * bk.y; s[2][2] += aq.z * bk.z; s[2][3] += aq.z * bk.w;
            s[3][0] += aq.w * bk.x; s[3][1] += aq.w * bk.y; s[3][2] += aq.w * bk.z; s[3][3] += aq.w * bk.w;
        }

        // online softmax (row stats shared across the 16 lanes of a row group)
        #pragma unroll
        for (int ri = 0; ri < 4; ri++) {
            float tmax = fmaxf(fmaxf(s[ri][0], s[ri][1]), fmaxf(s[ri][2], s[ri][3]));
            #pragma unroll
            for (int off = 1; off < 16; off <<= 1)
                tmax = fmaxf(tmax, __shfl_xor_sync(0xffffffffu, tmax, off));
            float mn    = fmaxf(m[ri], tmax);
            float alpha = __expf(m[ri] - mn);
            m[ri] = mn;
            float ps = 0.0f;
            #pragma unroll
            for (int ci = 0; ci < 4; ci++) {
                float pv = __expf(s[ri][ci] - mn);
                s[ri][ci] = pv;
                ps += pv;
            }
            #pragma unroll
            for (int off = 1; off < 16; off <<= 1)
                ps += __shfl_xor_sync(0xffffffffu, ps, off);
            l[ri] = l[ri] * alpha + ps;
            #pragma unroll
            for (int ci = 0; ci < 4; ci++) o[ri][ci] *= alpha;
            *(float4*)&Ps[(rgrp * 4 + ri) * 64 + cgrp * 4] =
                make_float4(s[ri][0], s[ri][1], s[ri][2], s[ri][3]);
        }
        __syncwarp();   // Ps consumed only within the producing warp's row groups

        // O += P @ V
        #pragma unroll 4
        for (int j4 = 0; j4 < 16; j4++) {
            float pr[4][4];
            #pragma unroll
            for (int ri = 0; ri < 4; ri++)
                *(float4*)&pr[ri][0] = *(const float4*)&Ps[(rgrp * 4 + ri) * 64 + j4 * 4];
            #pragma unroll
            for (int jj = 0; jj < 4; jj++) {
                float4 v = *(const float4*)&Vs[(j4 * 4 + jj) * 64 + cgrp * 4];
                #pragma unroll
                for (int ri = 0; ri < 4; ri++) {
                    o[ri][0] += pr[ri][jj] * v.x;
                    o[ri][1] += pr[ri][jj] * v.y;
                    o[ri][2] += pr[ri][jj] * v.z;
                    o[ri][3] += pr[ri][jj] * v.w;
                }
            }
        }
    }

    // epilogue: write [b][n][h*64+d] layout for the out-proj GEMM
    const int b_ = bh >> 4;
    const int h  = bh & 15;
    #pragma unroll
    for (int ri = 0; ri < 4; ri++) {
        float inv = 1.0f / l[ri];
        int nn = qt * 64 + rgrp * 4 + ri;
        float4 res = make_float4(o[ri][0] * inv, o[ri][1] * inv, o[ri][2] * inv, o[ri][3] * inv);
        *(float4*)&g_attn[(size_t)(b_ * NSEQ + nn) * INNER + h * DHEAD + cgrp * 4] = res;
    }
}

// =================================================================================
// GEMM 2: out = attn @ w_out + b_out   (M=4096, N=1024, K=1024)
// =================================================================================
__global__ __launch_bounds__(256) void out_gemm_kernel(const float* __restrict__ B,
                                                       const float* __restrict__ bias,
                                                       float* __restrict__ C)
{
    __shared__ float As[8][128];
    __shared__ float Bs[8][128];

    const int tid  = threadIdx.x;
    const int ty   = tid >> 4;
    const int tx   = tid & 15;
    const int arow = tid >> 1;
    const int ac4  = (tid & 1) << 2;
    const int brow = tid >> 5;
    const int bc4  = (tid & 31) << 2;

    const float* Ap = g_attn + (blockIdx.y * 128 + arow) * KDIM + ac4;
    const float* Bp = B + brow * INNER + blockIdx.x * 128 + bc4;

    float acc[8][8];
    #pragma unroll
    for (int i = 0; i < 8; i++)
        #pragma unroll
        for (int j = 0; j < 8; j++) acc[i][j] = 0.0f;

    for (int k0 = 0; k0 < KDIM; k0 += 8) {
        float4 av = *(const float4*)(Ap + k0);
        float4 bv = *(const float4*)(Bp + (size_t)k0 * INNER);
        As[ac4 + 0][arow] = av.x;
        As[ac4 + 1][arow] = av.y;
        As[ac4 + 2][arow] = av.z;
        As[ac4 + 3][arow] = av.w;
        *(float4*)&Bs[brow][bc4] = bv;
        __syncthreads();

        #pragma unroll
        for (int kk = 0; kk < 8; kk++) {
            float a[8], b[8];
            *(float4*)&a[0] = *(const float4*)&As[kk][ty * 8];
            *(float4*)&a[4] = *(const float4*)&As[kk][ty * 8 + 4];
            *(float4*)&b[0] = *(const float4*)&Bs[kk][tx * 8];
            *(float4*)&b[4] = *(const float4*)&Bs[kk][tx * 8 + 4];
            #pragma unroll
            for (int i = 0; i < 8; i++)
                #pragma unroll
                for (int j = 0; j < 8; j++)
                    acc[i][j] += a[i] * b[j];
        }
        __syncthreads();
    }

    const int col0 = blockIdx.x * 128 + tx * 8;
    float4 bb0 = *(const float4*)(bias + col0);
    float4 bb1 = *(const float4*)(bias + col0 + 4);
    #pragma unroll
    for (int i = 0; i < 8; i++) {
        int row = blockIdx.y * 128 + ty * 8 + i;
        float4 v0 = make_float4(acc[i][0] + bb0.x, acc[i][1] + bb0.y, acc[i][2] + bb0.z, acc[i][3] + bb0.w);
        float4 v1 = make_float4(acc[i][4] + bb1.x, acc[i][5] + bb1.y, acc[i][6] + bb1.z, acc[i][7] + bb1.w);
        *(float4*)(C + (size_t)row * INNER + col0)     = v0;
        *(float4*)(C + (size_t)row * INNER + col0 + 4) = v1;
    }
}

// =================================================================================
extern "C" void kernel_launch(void* const* d_in, const int* in_sizes, int n_in,
                              void* d_out, int out_size)
{
    const float* x     = (const float*)d_in[0];
    const float* w_qkv = (const float*)d_in[1];
    const float* w_out = (const float*)d_in[2];
    const float* b_out = (const float*)d_in[3];
    float* out = (float*)d_out;

    // 64KB dynamic smem for attention (non-stream API; graph-capture safe)
    cudaFuncSetAttribute(attn_kernel, cudaFuncAttributeMaxDynamicSharedMemorySize, 65536);

    qkv_gemm_kernel<<<dim3(NQKV / 128, MTOK / 128), 256>>>(x, w_qkv);
    rope_kernel<<<(NB * HEADS * NSEQ * 32) / 256, 256>>>();
    attn_kernel<<<dim3(NSEQ / 64, NB * HEADS), 256, 65536>>>();
    out_gemm_kernel<<<dim3(INNER / 128, MTOK / 128), 256>>>(w_out, b_out, out);
}

// round 7
// speedup vs baseline: 1.3102x; 1.3102x over previous
#include <cuda_runtime.h>
#include <cuda_bf16.h>
#include <cstdint>

#define HEADS 16
#define DHEAD 64
#define NSEQ  2048
#define NB    2
#define INNER 1024
#define NQKV  3072
#define MTOK  4096
#define KDIM  1024

// ---------------- scratch (device globals; no runtime allocation) ----------------
__device__ float g_q[NB * HEADS * NSEQ * DHEAD];
__device__ float g_k[NB * HEADS * NSEQ * DHEAD];
__device__ float g_v[NB * HEADS * NSEQ * DHEAD];

__device__ __nv_bfloat16 g_xhi[MTOK * KDIM];
__device__ __nv_bfloat16 g_xlo[MTOK * KDIM];
__device__ __nv_bfloat16 g_wqkvT_hi[NQKV * KDIM];   // [n][k] = w_qkv[k][n]
__device__ __nv_bfloat16 g_wqkvT_lo[NQKV * KDIM];
__device__ __nv_bfloat16 g_woutT_hi[INNER * KDIM];
__device__ __nv_bfloat16 g_woutT_lo[INNER * KDIM];
__device__ __nv_bfloat16 g_ahi[MTOK * INNER];       // attention out, hi/lo bf16
__device__ __nv_bfloat16 g_alo[MTOK * INNER];

__device__ __forceinline__ void split2(float v, __nv_bfloat16& h, __nv_bfloat16& l) {
    h = __float2bfloat16(v);
    l = __float2bfloat16(v - __bfloat162float(h));
}

// mma.sync m16n8k16 bf16 -> fp32 (supported on compute_103 without 'a' features)
__device__ __forceinline__ void mma16816(float* c, const uint32_t* a, const uint32_t* b) {
    asm volatile(
        "mma.sync.aligned.m16n8k16.row.col.f32.bf16.bf16.f32 "
        "{%0,%1,%2,%3}, {%4,%5,%6,%7}, {%8,%9}, {%0,%1,%2,%3};"
        : "+f"(c[0]), "+f"(c[1]), "+f"(c[2]), "+f"(c[3])
        : "r"(a[0]), "r"(a[1]), "r"(a[2]), "r"(a[3]), "r"(b[0]), "r"(b[1]));
}

// ============================ conversion kernels ============================
__global__ __launch_bounds__(256) void split_x_kernel(const float* __restrict__ x)
{
    int idx = (blockIdx.x * 256 + threadIdx.x) * 4;
    float4 v = *(const float4*)(x + idx);
    __nv_bfloat16 h0, h1, h2, h3, l0, l1, l2, l3;
    split2(v.x, h0, l0); split2(v.y, h1, l1); split2(v.z, h2, l2); split2(v.w, h3, l3);
    *(__nv_bfloat162*)(g_xhi + idx)     = __nv_bfloat162(h0, h1);
    *(__nv_bfloat162*)(g_xhi + idx + 2) = __nv_bfloat162(h2, h3);
    *(__nv_bfloat162*)(g_xlo + idx)     = __nv_bfloat162(l0, l1);
    *(__nv_bfloat162*)(g_xlo + idx + 2) = __nv_bfloat162(l2, l3);
}

// W [K][N] fp32 -> WT[N][K] bf16 hi/lo.  WHICH 0: w_qkv (N=3072), WHICH 1: w_out (N=1024).
// Device-global destinations selected INSIDE device code (host must not pass symbol addrs).
template<int WHICH>
__global__ __launch_bounds__(256) void transpose_split_kernel(const float* __restrict__ W)
{
    const int N = (WHICH == 0) ? NQKV : INNER;
    __nv_bfloat16* WTh = (WHICH == 0) ? g_wqkvT_hi : g_woutT_hi;
    __nv_bfloat16* WTl = (WHICH == 0) ? g_wqkvT_lo : g_woutT_lo;

    __shared__ float tile[32][33];
    int tx = threadIdx.x & 31, ty = threadIdx.x >> 5;
    int bn = blockIdx.x, bk = blockIdx.y;
    #pragma unroll
    for (int i = 0; i < 4; i++)
        tile[ty + 8 * i][tx] = W[(size_t)(bk * 32 + ty + 8 * i) * N + bn * 32 + tx];
    __syncthreads();
    #pragma unroll
    for (int i = 0; i < 4; i++) {
        float v = tile[tx][ty + 8 * i];
        __nv_bfloat16 h, l;
        split2(v, h, l);
        size_t o = (size_t)(bn * 32 + ty + 8 * i) * KDIM + bk * 32 + tx;
        WTh[o] = h; WTl[o] = l;
    }
}

// ============================ HMMA GEMM (mma.sync) ============================
// C[M, N-tile 128] = A @ B^T over 3 hi/lo K-segments (K_eff = 3072).
// Block 128x128, 8 warps (2m x 4n), warp tile 64x32, K-chunk 32, double buffer.
#define AS_STRIDE 40
#define NCHUNK 96               // 3 segs * (1024/32)

// MODE 0: A=g_x*, B=g_wqkvT*, scatter to g_q/g_k/g_v (q scaled).
// MODE 1: A=g_a*, B=g_woutT*, out-proj + bias -> Cout.
template<int MODE>
__global__ __launch_bounds__(256) void mma_gemm_kernel(const float* __restrict__ bias,
                                                       float* __restrict__ Cout)
{
    // device-side global selection (the round-4 bug was passing these from host)
    const __nv_bfloat16* __restrict__ Ahi = (MODE == 0) ? g_xhi : g_ahi;
    const __nv_bfloat16* __restrict__ Alo = (MODE == 0) ? g_xlo : g_alo;
    const __nv_bfloat16* __restrict__ Bhi = (MODE == 0) ? g_wqkvT_hi : g_woutT_hi;
    const __nv_bfloat16* __restrict__ Blo = (MODE == 0) ? g_wqkvT_lo : g_woutT_lo;

    __shared__ __align__(16) __nv_bfloat16 As[2][128 * AS_STRIDE];
    __shared__ __align__(16) __nv_bfloat16 Bs[2][128 * AS_STRIDE];

    const int tid  = threadIdx.x;
    const int lane = tid & 31, wid = tid >> 5;
    const int wm = wid & 1, wn = wid >> 1;       // warp 64x32 tile at (wm*64, wn*32)
    const int g  = lane >> 2, tg = lane & 3;
    const int bx = blockIdx.x, by = blockIdx.y;

    const int lrow = tid >> 2;                   // gmem load: rows lrow, lrow+64
    const int lc8  = (tid & 3) * 8;              // 8-bf16 chunk

    float acc[4][4][4];
    #pragma unroll
    for (int mt = 0; mt < 4; mt++)
        #pragma unroll
        for (int nt = 0; nt < 4; nt++)
            #pragma unroll
            for (int r = 0; r < 4; r++) acc[mt][nt][r] = 0.0f;

    uint4 ra[2], rb[2];

    // prologue: chunk 0 (seg 0: Ahi x Bhi)
    #pragma unroll
    for (int i = 0; i < 2; i++) {
        int row = lrow + i * 64;
        ra[i] = *(const uint4*)(Ahi + (size_t)(by * 128 + row) * KDIM + lc8);
        rb[i] = *(const uint4*)(Bhi + (size_t)(bx * 128 + row) * KDIM + lc8);
    }
    #pragma unroll
    for (int i = 0; i < 2; i++) {
        int row = lrow + i * 64;
        *(uint4*)&As[0][row * AS_STRIDE + lc8] = ra[i];
        *(uint4*)&Bs[0][row * AS_STRIDE + lc8] = rb[i];
    }
    __syncthreads();

    int buf = 0;
    for (int c = 0; c < NCHUNK; c++) {
        // prefetch chunk c+1
        if (c + 1 < NCHUNK) {
            int cn  = c + 1;
            int seg = cn >> 5;
            int kk  = (cn & 31) * 32;
            const __nv_bfloat16* Asrc = (seg == 1) ? Alo : Ahi;
            const __nv_bfloat16* Bsrc = (seg == 2) ? Blo : Bhi;
            #pragma unroll
            for (int i = 0; i < 2; i++) {
                int row = lrow + i * 64;
                ra[i] = *(const uint4*)(Asrc + (size_t)(by * 128 + row) * KDIM + kk + lc8);
                rb[i] = *(const uint4*)(Bsrc + (size_t)(bx * 128 + row) * KDIM + kk + lc8);
            }
        }

        // compute on smem[buf]: 2 k-steps of 16
        #pragma unroll
        for (int ks = 0; ks < 2; ks++) {
            const int kc = ks * 16;
            uint32_t a[4][4], b[4][2];
            #pragma unroll
            for (int mt = 0; mt < 4; mt++) {
                int r0 = wm * 64 + mt * 16;
                a[mt][0] = *(const uint32_t*)&As[buf][(r0 + g)     * AS_STRIDE + kc + tg * 2];
                a[mt][1] = *(const uint32_t*)&As[buf][(r0 + g + 8) * AS_STRIDE + kc + tg * 2];
                a[mt][2] = *(const uint32_t*)&As[buf][(r0 + g)     * AS_STRIDE + kc + tg * 2 + 8];
                a[mt][3] = *(const uint32_t*)&As[buf][(r0 + g + 8) * AS_STRIDE + kc + tg * 2 + 8];
            }
            #pragma unroll
            for (int nt = 0; nt < 4; nt++) {
                int n0 = wn * 32 + nt * 8;
                b[nt][0] = *(const uint32_t*)&Bs[buf][(n0 + g) * AS_STRIDE + kc + tg * 2];
                b[nt][1] = *(const uint32_t*)&Bs[buf][(n0 + g) * AS_STRIDE + kc + tg * 2 + 8];
            }
            #pragma unroll
            for (int mt = 0; mt < 4; mt++)
                #pragma unroll
                for (int nt = 0; nt < 4; nt++)
                    mma16816(acc[mt][nt], a[mt], b[nt]);
        }

        if (c + 1 < NCHUNK) {
            __syncthreads();
            #pragma unroll
            for (int i = 0; i < 2; i++) {
                int row = lrow + i * 64;
                *(uint4*)&As[buf ^ 1][row * AS_STRIDE + lc8] = ra[i];
                *(uint4*)&Bs[buf ^ 1][row * AS_STRIDE + lc8] = rb[i];
            }
            __syncthreads();
            buf ^= 1;
        }
    }

    // epilogue
    #pragma unroll
    for (int mt = 0; mt < 4; mt++) {
        #pragma unroll
        for (int nt = 0; nt < 4; nt++) {
            int row0 = by * 128 + wm * 64 + mt * 16 + g;
            int col  = bx * 128 + wn * 32 + nt * 8 + tg * 2;
            if (MODE == 0) {
                const int sidx = col >> 10;
                const int h    = (col >> 6) & 15;
                const int d0   = col & 63;
                const float mul = (sidx == 0) ? 0.125f : 1.0f;
                float* dst = (sidx == 0) ? g_q : (sidx == 1) ? g_k : g_v;
                #pragma unroll
                for (int rr = 0; rr < 2; rr++) {
                    int row = row0 + rr * 8;
                    int b_ = row >> 11, nn = row & 2047;
                    float2 val = make_float2(acc[mt][nt][2 * rr] * mul, acc[mt][nt][2 * rr + 1] * mul);
                    *(float2*)(dst + (((b_ * HEADS + h) * NSEQ + nn) * DHEAD + d0)) = val;
                }
            } else {
                float2 bb = *(const float2*)(bias + col);
                #pragma unroll
                for (int rr = 0; rr < 2; rr++) {
                    int row = row0 + rr * 8;
                    float2 val = make_float2(acc[mt][nt][2 * rr] + bb.x, acc[mt][nt][2 * rr + 1] + bb.y);
                    *(float2*)(Cout + (size_t)row * INNER + col) = val;
                }
            }
        }
    }
}

// ============================ RoPE ============================
__global__ __launch_bounds__(256) void rope_kernel()
{
    int idx = blockIdx.x * blockDim.x + threadIdx.x;
    int d  = idx & 31;
    int nn = (idx >> 5) & 2047;
    int bh = idx >> 16;

    float theta = __powf(10000.0f, -(float)d * (1.0f / 32.0f));
    float ang = (float)nn * theta;
    float sv, cv;
    sincosf(ang, &sv, &cv);

    int base = (bh * NSEQ + nn) * DHEAD + d;
    {
        float x1 = g_q[base], x2 = g_q[base + 32];
        g_q[base]      = x1 * cv - x2 * sv;
        g_q[base + 32] = x1 * sv + x2 * cv;
    }
    {
        float x1 = g_k[base], x2 = g_k[base + 32];
        g_k[base]      = x1 * cv - x2 * sv;
        g_k[base + 32] = x1 * sv + x2 * cv;
    }
}

// ============================ flash attention (fp32, epilogue -> bf16 hi/lo) ============================
__global__ __launch_bounds__(256) void attn_kernel()
{
    extern __shared__ float sm[];
    float* QsT = sm;
    float* KsT = sm + 4096;
    float* Vs  = sm + 8192;
    float* Ps  = sm + 12288;

    const int tid  = threadIdx.x;
    const int qt   = blockIdx.x;
    const int bh   = blockIdx.y;
    const int rgrp = tid >> 4;
    const int cgrp = tid & 15;

    const float* qp = g_q + (size_t)bh * NSEQ * DHEAD;
    const float* kp = g_k + (size_t)bh * NSEQ * DHEAD;
    const float* vp = g_v + (size_t)bh * NSEQ * DHEAD;

    #pragma unroll
    for (int i = 0; i < 4; i++) {
        int f = tid + i * 256;
        int r = f & 63;
        int c4 = (f >> 6) << 2;
        float4 v = *(const float4*)(qp + (qt * 64 + r) * DHEAD + c4);
        QsT[(c4 + 0) * 64 + r] = v.x;
        QsT[(c4 + 1) * 64 + r] = v.y;
        QsT[(c4 + 2) * 64 + r] = v.z;
        QsT[(c4 + 3) * 64 + r] = v.w;
    }

    float o[4][4];
    float m[4], l[4];
    #pragma unroll
    for (int ri = 0; ri < 4; ri++) {
        m[ri] = -1e30f; l[ri] = 0.0f;
        #pragma unroll
        for (int ci = 0; ci < 4; ci++) o[ri][ci] = 0.0f;
    }

    for (int kt = 0; kt < NSEQ / 64; kt++) {
        __syncthreads();
        #pragma unroll
        for (int i = 0; i < 4; i++) {
            int f = tid + i * 256;
            int r = f & 63;
            int c4 = (f >> 6) << 2;
            float4 v = *(const float4*)(kp + (kt * 64 + r) * DHEAD + c4);
            KsT[(c4 + 0) * 64 + r] = v.x;
            KsT[(c4 + 1) * 64 + r] = v.y;
            KsT[(c4 + 2) * 64 + r] = v.z;
            KsT[(c4 + 3) * 64 + r] = v.w;
        }
        #pragma unroll
        for (int i = 0; i < 4; i++) {
            int f = tid + i * 256;
            int r = f >> 4;
            int c4 = (f & 15) << 2;
            *(float4*)&Vs[r * 64 + c4] = *(const float4*)(vp + (kt * 64 + r) * DHEAD + c4);
        }
        __syncthreads();

        float s[4][4];
        #pragma unroll
        for (int ri = 0; ri < 4; ri++)
            #pragma unroll
            for (int ci = 0; ci < 4; ci++) s[ri][ci] = 0.0f;

        #pragma unroll 8
        for (int kd = 0; kd < 64; kd++) {
            float4 aq = *(const float4*)&QsT[kd * 64 + rgrp * 4];
            float4 bk = *(const float4*)&KsT[kd * 64 + cgrp * 4];
            s[0][0] += aq.x * bk.x; s[0][1] += aq.x * bk.y; s[0][2] += aq.x * bk.z; s[0][3] += aq.x * bk.w;
            s[1][0] += aq.y * bk.x; s[1][1] += aq.y * bk.y; s[1][2] += aq.y * bk.z; s[1][3] += aq.y * bk.w;
            s[2][0] += aq.z * bk.x; s[2][1] += aq.z * bk.y; s[2][2] += aq.z * bk.z; s[2][3] += aq.z * bk.w;
            s[3][0] += aq.w * bk.x; s[3][1] += aq.w * bk.y; s[3][2] += aq.w * bk.z; s[3][3] += aq.w * bk.w;
        }

        #pragma unroll
        for (int ri = 0; ri < 4; ri++) {
            float tmax = fmaxf(fmaxf(s[ri][0], s[ri][1]), fmaxf(s[ri][2], s[ri][3]));
            #pragma unroll
            for (int off = 1; off < 16; off <<= 1)
                tmax = fmaxf(tmax, __shfl_xor_sync(0xffffffffu, tmax, off));
            float mn    = fmaxf(m[ri], tmax);
            float alpha = __expf(m[ri] - mn);
            m[ri] = mn;
            float ps = 0.0f;
            #pragma unroll
            for (int ci = 0; ci < 4; ci++) {
                float pv = __expf(s[ri][ci] - mn);
                s[ri][ci] = pv;
                ps += pv;
            }
            #pragma unroll
            for (int off = 1; off < 16; off <<= 1)
                ps += __shfl_xor_sync(0xffffffffu, ps, off);
            l[ri] = l[ri] * alpha + ps;
            #pragma unroll
            for (int ci = 0; ci < 4; ci++) o[ri][ci] *= alpha;
            *(float4*)&Ps[(rgrp * 4 + ri) * 64 + cgrp * 4] =
                make_float4(s[ri][0], s[ri][1], s[ri][2], s[ri][3]);
        }
        __syncwarp();

        #pragma unroll 4
        for (int j4 = 0; j4 < 16; j4++) {
            float pr[4][4];
            #pragma unroll
            for (int ri = 0; ri < 4; ri++)
                *(float4*)&pr[ri][0] = *(const float4*)&Ps[(rgrp * 4 + ri) * 64 + j4 * 4];
            #pragma unroll
            for (int jj = 0; jj < 4; jj++) {
                float4 v = *(const float4*)&Vs[(j4 * 4 + jj) * 64 + cgrp * 4];
                #pragma unroll
                for (int ri = 0; ri < 4; ri++) {
                    o[ri][0] += pr[ri][jj] * v.x;
                    o[ri][1] += pr[ri][jj] * v.y;
                    o[ri][2] += pr[ri][jj] * v.z;
                    o[ri][3] += pr[ri][jj] * v.w;
                }
            }
        }
    }

    const int b_ = bh >> 4;
    const int h  = bh & 15;
    #pragma unroll
    for (int ri = 0; ri < 4; ri++) {
        float inv = 1.0f / l[ri];
        int nn = qt * 64 + rgrp * 4 + ri;
        size_t base = (size_t)(b_ * NSEQ + nn) * INNER + h * DHEAD + cgrp * 4;
        #pragma unroll
        for (int ci = 0; ci < 4; ci++) {
            float v = o[ri][ci] * inv;
            __nv_bfloat16 hh, ll;
            split2(v, hh, ll);
            g_ahi[base + ci] = hh;
            g_alo[base + ci] = ll;
        }
    }
}

// ============================ launch ============================
extern "C" void kernel_launch(void* const* d_in, const int* in_sizes, int n_in,
                              void* d_out, int out_size)
{
    const float* x     = (const float*)d_in[0];
    const float* w_qkv = (const float*)d_in[1];
    const float* w_out = (const float*)d_in[2];
    const float* b_out = (const float*)d_in[3];
    float* out = (float*)d_out;

    cudaFuncSetAttribute(attn_kernel, cudaFuncAttributeMaxDynamicSharedMemorySize, 65536);

    // input conversions (device-global destinations selected in device code)
    split_x_kernel<<<MTOK * KDIM / 4 / 256, 256>>>(x);
    transpose_split_kernel<0><<<dim3(NQKV / 32, KDIM / 32), 256>>>(w_qkv);
    transpose_split_kernel<1><<<dim3(INNER / 32, KDIM / 32), 256>>>(w_out);

    // qkv = x @ w_qkv (split bf16, HMMA) -> scatter to g_q/g_k/g_v
    mma_gemm_kernel<0><<<dim3(NQKV / 128, MTOK / 128), 256>>>(nullptr, nullptr);

    rope_kernel<<<(NB * HEADS * NSEQ * 32) / 256, 256>>>();
    attn_kernel<<<dim3(NSEQ / 64, NB * HEADS), 256, 65536>>>();

    // out = attn @ w_out + b_out
    mma_gemm_kernel<1><<<dim3(INNER / 128, MTOK / 128), 256>>>(b_out, out);
}

// round 8
// speedup vs baseline: 2.3095x; 1.7627x over previous
#include <cuda_runtime.h>
#include <cuda_bf16.h>
#include <cuda_fp16.h>
#include <cstdint>

#define HEADS 16
#define DHEAD 64
#define NSEQ  2048
#define NB    2
#define INNER 1024
#define NQKV  3072
#define MTOK  4096
#define KDIM  1024

// ---------------- scratch (device globals; no runtime allocation) ----------------
__device__ float g_q[NB * HEADS * NSEQ * DHEAD];
__device__ float g_k[NB * HEADS * NSEQ * DHEAD];
__device__ float g_v[NB * HEADS * NSEQ * DHEAD];

__device__ __nv_bfloat16 g_xhi[MTOK * KDIM];
__device__ __nv_bfloat16 g_xlo[MTOK * KDIM];
__device__ __nv_bfloat16 g_wqkvT_hi[NQKV * KDIM];
__device__ __nv_bfloat16 g_wqkvT_lo[NQKV * KDIM];
__device__ __nv_bfloat16 g_woutT_hi[INNER * KDIM];
__device__ __nv_bfloat16 g_woutT_lo[INNER * KDIM];
__device__ __nv_bfloat16 g_ahi[MTOK * INNER];
__device__ __nv_bfloat16 g_alo[MTOK * INNER];

// attention operands (prepared by rope_split / v_prep)
__device__ __nv_bfloat16 g_qhi[NB * HEADS * NSEQ * DHEAD];
__device__ __nv_bfloat16 g_qlo[NB * HEADS * NSEQ * DHEAD];
__device__ __nv_bfloat16 g_khi[NB * HEADS * NSEQ * DHEAD];
__device__ __nv_bfloat16 g_klo[NB * HEADS * NSEQ * DHEAD];
__device__ __half        g_vT16[NB * HEADS * DHEAD * NSEQ];   // [bh][d][n]

__device__ __forceinline__ void split2(float v, __nv_bfloat16& h, __nv_bfloat16& l) {
    h = __float2bfloat16(v);
    l = __float2bfloat16(v - __bfloat162float(h));
}

// mma.sync m16n8k16 bf16 -> fp32
__device__ __forceinline__ void mma16816(float* c, const uint32_t* a, const uint32_t* b) {
    asm volatile(
        "mma.sync.aligned.m16n8k16.row.col.f32.bf16.bf16.f32 "
        "{%0,%1,%2,%3}, {%4,%5,%6,%7}, {%8,%9}, {%0,%1,%2,%3};"
        : "+f"(c[0]), "+f"(c[1]), "+f"(c[2]), "+f"(c[3])
        : "r"(a[0]), "r"(a[1]), "r"(a[2]), "r"(a[3]), "r"(b[0]), "r"(b[1]));
}
// mma.sync m16n8k16 fp16 -> fp32
__device__ __forceinline__ void mma16816h(float* c, const uint32_t* a, const uint32_t* b) {
    asm volatile(
        "mma.sync.aligned.m16n8k16.row.col.f32.f16.f16.f32 "
        "{%0,%1,%2,%3}, {%4,%5,%6,%7}, {%8,%9}, {%0,%1,%2,%3};"
        : "+f"(c[0]), "+f"(c[1]), "+f"(c[2]), "+f"(c[3])
        : "r"(a[0]), "r"(a[1]), "r"(a[2]), "r"(a[3]), "r"(b[0]), "r"(b[1]));
}

// ============================ conversion kernels ============================
__global__ __launch_bounds__(256) void split_x_kernel(const float* __restrict__ x)
{
    int idx = (blockIdx.x * 256 + threadIdx.x) * 4;
    float4 v = *(const float4*)(x + idx);
    __nv_bfloat16 h0, h1, h2, h3, l0, l1, l2, l3;
    split2(v.x, h0, l0); split2(v.y, h1, l1); split2(v.z, h2, l2); split2(v.w, h3, l3);
    *(__nv_bfloat162*)(g_xhi + idx)     = __nv_bfloat162(h0, h1);
    *(__nv_bfloat162*)(g_xhi + idx + 2) = __nv_bfloat162(h2, h3);
    *(__nv_bfloat162*)(g_xlo + idx)     = __nv_bfloat162(l0, l1);
    *(__nv_bfloat162*)(g_xlo + idx + 2) = __nv_bfloat162(l2, l3);
}

template<int WHICH>
__global__ __launch_bounds__(256) void transpose_split_kernel(const float* __restrict__ W)
{
    const int N = (WHICH == 0) ? NQKV : INNER;
    __nv_bfloat16* WTh = (WHICH == 0) ? g_wqkvT_hi : g_woutT_hi;
    __nv_bfloat16* WTl = (WHICH == 0) ? g_wqkvT_lo : g_woutT_lo;

    __shared__ float tile[32][33];
    int tx = threadIdx.x & 31, ty = threadIdx.x >> 5;
    int bn = blockIdx.x, bk = blockIdx.y;
    #pragma unroll
    for (int i = 0; i < 4; i++)
        tile[ty + 8 * i][tx] = W[(size_t)(bk * 32 + ty + 8 * i) * N + bn * 32 + tx];
    __syncthreads();
    #pragma unroll
    for (int i = 0; i < 4; i++) {
        float v = tile[tx][ty + 8 * i];
        __nv_bfloat16 h, l;
        split2(v, h, l);
        size_t o = (size_t)(bn * 32 + ty + 8 * i) * KDIM + bk * 32 + tx;
        WTh[o] = h; WTl[o] = l;
    }
}

// ============================ HMMA GEMM (unchanged from R7) ============================
#define AS_STRIDE 40
#define NCHUNK 96

template<int MODE>
__global__ __launch_bounds__(256) void mma_gemm_kernel(const float* __restrict__ bias,
                                                       float* __restrict__ Cout)
{
    const __nv_bfloat16* __restrict__ Ahi = (MODE == 0) ? g_xhi : g_ahi;
    const __nv_bfloat16* __restrict__ Alo = (MODE == 0) ? g_xlo : g_alo;
    const __nv_bfloat16* __restrict__ Bhi = (MODE == 0) ? g_wqkvT_hi : g_woutT_hi;
    const __nv_bfloat16* __restrict__ Blo = (MODE == 0) ? g_wqkvT_lo : g_woutT_lo;

    __shared__ __align__(16) __nv_bfloat16 As[2][128 * AS_STRIDE];
    __shared__ __align__(16) __nv_bfloat16 Bs[2][128 * AS_STRIDE];

    const int tid  = threadIdx.x;
    const int lane = tid & 31, wid = tid >> 5;
    const int wm = wid & 1, wn = wid >> 1;
    const int g  = lane >> 2, tg = lane & 3;
    const int bx = blockIdx.x, by = blockIdx.y;

    const int lrow = tid >> 2;
    const int lc8  = (tid & 3) * 8;

    float acc[4][4][4];
    #pragma unroll
    for (int mt = 0; mt < 4; mt++)
        #pragma unroll
        for (int nt = 0; nt < 4; nt++)
            #pragma unroll
            for (int r = 0; r < 4; r++) acc[mt][nt][r] = 0.0f;

    uint4 ra[2], rb[2];
    #pragma unroll
    for (int i = 0; i < 2; i++) {
        int row = lrow + i * 64;
        ra[i] = *(const uint4*)(Ahi + (size_t)(by * 128 + row) * KDIM + lc8);
        rb[i] = *(const uint4*)(Bhi + (size_t)(bx * 128 + row) * KDIM + lc8);
    }
    #pragma unroll
    for (int i = 0; i < 2; i++) {
        int row = lrow + i * 64;
        *(uint4*)&As[0][row * AS_STRIDE + lc8] = ra[i];
        *(uint4*)&Bs[0][row * AS_STRIDE + lc8] = rb[i];
    }
    __syncthreads();

    int buf = 0;
    for (int c = 0; c < NCHUNK; c++) {
        if (c + 1 < NCHUNK) {
            int cn  = c + 1;
            int seg = cn >> 5;
            int kk  = (cn & 31) * 32;
            const __nv_bfloat16* Asrc = (seg == 1) ? Alo : Ahi;
            const __nv_bfloat16* Bsrc = (seg == 2) ? Blo : Bhi;
            #pragma unroll
            for (int i = 0; i < 2; i++) {
                int row = lrow + i * 64;
                ra[i] = *(const uint4*)(Asrc + (size_t)(by * 128 + row) * KDIM + kk + lc8);
                rb[i] = *(const uint4*)(Bsrc + (size_t)(bx * 128 + row) * KDIM + kk + lc8);
            }
        }

        #pragma unroll
        for (int ks = 0; ks < 2; ks++) {
            const int kc = ks * 16;
            uint32_t a[4][4], b[4][2];
            #pragma unroll
            for (int mt = 0; mt < 4; mt++) {
                int r0 = wm * 64 + mt * 16;
                a[mt][0] = *(const uint32_t*)&As[buf][(r0 + g)     * AS_STRIDE + kc + tg * 2];
                a[mt][1] = *(const uint32_t*)&As[buf][(r0 + g + 8) * AS_STRIDE + kc + tg * 2];
                a[mt][2] = *(const uint32_t*)&As[buf][(r0 + g)     * AS_STRIDE + kc + tg * 2 + 8];
                a[mt][3] = *(const uint32_t*)&As[buf][(r0 + g + 8) * AS_STRIDE + kc + tg * 2 + 8];
            }
            #pragma unroll
            for (int nt = 0; nt < 4; nt++) {
                int n0 = wn * 32 + nt * 8;
                b[nt][0] = *(const uint32_t*)&Bs[buf][(n0 + g) * AS_STRIDE + kc + tg * 2];
                b[nt][1] = *(const uint32_t*)&Bs[buf][(n0 + g) * AS_STRIDE + kc + tg * 2 + 8];
            }
            #pragma unroll
            for (int mt = 0; mt < 4; mt++)
                #pragma unroll
                for (int nt = 0; nt < 4; nt++)
                    mma16816(acc[mt][nt], a[mt], b[nt]);
        }

        if (c + 1 < NCHUNK) {
            __syncthreads();
            #pragma unroll
            for (int i = 0; i < 2; i++) {
                int row = lrow + i * 64;
                *(uint4*)&As[buf ^ 1][row * AS_STRIDE + lc8] = ra[i];
                *(uint4*)&Bs[buf ^ 1][row * AS_STRIDE + lc8] = rb[i];
            }
            __syncthreads();
            buf ^= 1;
        }
    }

    #pragma unroll
    for (int mt = 0; mt < 4; mt++) {
        #pragma unroll
        for (int nt = 0; nt < 4; nt++) {
            int row0 = by * 128 + wm * 64 + mt * 16 + g;
            int col  = bx * 128 + wn * 32 + nt * 8 + tg * 2;
            if (MODE == 0) {
                const int sidx = col >> 10;
                const int h    = (col >> 6) & 15;
                const int d0   = col & 63;
                const float mul = (sidx == 0) ? 0.125f : 1.0f;
                float* dst = (sidx == 0) ? g_q : (sidx == 1) ? g_k : g_v;
                #pragma unroll
                for (int rr = 0; rr < 2; rr++) {
                    int row = row0 + rr * 8;
                    int b_ = row >> 11, nn = row & 2047;
                    float2 val = make_float2(acc[mt][nt][2 * rr] * mul, acc[mt][nt][2 * rr + 1] * mul);
                    *(float2*)(dst + (((b_ * HEADS + h) * NSEQ + nn) * DHEAD + d0)) = val;
                }
            } else {
                float2 bb = *(const float2*)(bias + col);
                #pragma unroll
                for (int rr = 0; rr < 2; rr++) {
                    int row = row0 + rr * 8;
                    float2 val = make_float2(acc[mt][nt][2 * rr] + bb.x, acc[mt][nt][2 * rr + 1] + bb.y);
                    *(float2*)(Cout + (size_t)row * INNER + col) = val;
                }
            }
        }
    }
}

// ============================ RoPE + hi/lo bf16 split for Q,K ============================
__global__ __launch_bounds__(256) void rope_split_kernel()
{
    int idx = blockIdx.x * blockDim.x + threadIdx.x;   // 2^21
    int d  = idx & 31;
    int nn = (idx >> 5) & 2047;
    int bh = idx >> 16;

    float theta = __powf(10000.0f, -(float)d * (1.0f / 32.0f));
    float ang = (float)nn * theta;
    float sv, cv;
    sincosf(ang, &sv, &cv);

    int base = (bh * NSEQ + nn) * DHEAD + d;
    {
        float x1 = g_q[base], x2 = g_q[base + 32];
        float r1 = x1 * cv - x2 * sv;
        float r2 = x1 * sv + x2 * cv;
        __nv_bfloat16 h, l;
        split2(r1, h, l); g_qhi[base] = h;      g_qlo[base] = l;
        split2(r2, h, l); g_qhi[base + 32] = h; g_qlo[base + 32] = l;
    }
    {
        float x1 = g_k[base], x2 = g_k[base + 32];
        float r1 = x1 * cv - x2 * sv;
        float r2 = x1 * sv + x2 * cv;
        __nv_bfloat16 h, l;
        split2(r1, h, l); g_khi[base] = h;      g_klo[base] = l;
        split2(r2, h, l); g_khi[base + 32] = h; g_klo[base + 32] = l;
    }
}

// ============================ V transpose -> fp16 [bh][d][n] ============================
__global__ __launch_bounds__(256) void v_prep_kernel()
{
    __shared__ float tile[32][33];
    int tx = threadIdx.x & 31, ty = threadIdx.x >> 5;
    int n0 = blockIdx.x * 32, d0 = blockIdx.y * 32, bh = blockIdx.z;
    #pragma unroll
    for (int i = 0; i < 4; i++)
        tile[ty + 8 * i][tx] = g_v[((size_t)bh * NSEQ + n0 + ty + 8 * i) * DHEAD + d0 + tx];
    __syncthreads();
    #pragma unroll
    for (int i = 0; i < 4; i++)
        g_vT16[((size_t)bh * DHEAD + d0 + ty + 8 * i) * NSEQ + n0 + tx] =
            __float2half(tile[tx][ty + 8 * i]);
}

// ============================ HMMA flash attention ============================
// Block = (bh, 128-query tile). 8 warps: wm = wid&1 (q half), wn = wid>>1.
// QK^T: 3-seg bf16 hi/lo split; softmax fp32; PV: single fp16 MMA.
#define QS 72          // Q/K smem stride (bf16 elems); 36 words = 4 banks mod 32
#define PS 136         // Ps/VT smem stride (fp16 elems); 68 words = 4 banks mod 32

#define SM_QHI  0
#define SM_QLO  (SM_QHI + 128 * QS * 2)
#define SM_KHI  (SM_QLO + 128 * QS * 2)
#define SM_KLO  (SM_KHI + 128 * QS * 2)
#define SM_VT   (SM_KLO + 128 * QS * 2)
#define SM_PS   (SM_VT + 64 * PS * 2)
#define SM_PMAX (SM_PS + 128 * PS * 2)
#define SM_PSUM (SM_PMAX + 128 * 4 * 4)
#define SM_MROW (SM_PSUM + 128 * 4 * 4)
#define SM_LROW (SM_MROW + 128 * 4)
#define SM_ALPH (SM_LROW + 128 * 4)
#define SM_ATTN (SM_ALPH + 128 * 4)          // 131584 bytes

__global__ __launch_bounds__(256, 1) void attn_mma_kernel()
{
    extern __shared__ __align__(16) char smc[];
    __nv_bfloat16* Qh = (__nv_bfloat16*)(smc + SM_QHI);
    __nv_bfloat16* Ql = (__nv_bfloat16*)(smc + SM_QLO);
    __nv_bfloat16* Kh = (__nv_bfloat16*)(smc + SM_KHI);
    __nv_bfloat16* Kl = (__nv_bfloat16*)(smc + SM_KLO);
    __half*        Vt = (__half*)(smc + SM_VT);
    __half*        Pp = (__half*)(smc + SM_PS);
    float* pmax  = (float*)(smc + SM_PMAX);
    float* psum  = (float*)(smc + SM_PSUM);
    float* m_row = (float*)(smc + SM_MROW);
    float* l_row = (float*)(smc + SM_LROW);
    float* alph  = (float*)(smc + SM_ALPH);

    const int tid  = threadIdx.x;
    const int lane = tid & 31, wid = tid >> 5;
    const int wm = wid & 1, wn = wid >> 1;
    const int g  = lane >> 2, tg = lane & 3;
    const int qt = blockIdx.x, bh = blockIdx.y;

    const size_t qkbase = (size_t)bh * NSEQ * DHEAD;

    // load Q tile (rows qt*128..+127) hi/lo
    #pragma unroll
    for (int i = 0; i < 4; i++) {
        int f = tid + i * 256;
        int row = f >> 3, c8 = (f & 7) * 8;
        size_t src = qkbase + (size_t)(qt * 128 + row) * DHEAD + c8;
        *(uint4*)&Qh[row * QS + c8] = *(const uint4*)(g_qhi + src);
        *(uint4*)&Ql[row * QS + c8] = *(const uint4*)(g_qlo + src);
    }
    if (tid < 128) { m_row[tid] = -1e30f; l_row[tid] = 0.0f; }

    float o[4][2][4];
    #pragma unroll
    for (int mt = 0; mt < 4; mt++)
        #pragma unroll
        for (int nt = 0; nt < 2; nt++)
            #pragma unroll
            for (int r = 0; r < 4; r++) o[mt][nt][r] = 0.0f;

    for (int kt = 0; kt < NSEQ / 128; kt++) {
        __syncthreads();   // prev iter's PV reads of Vt/Pp done; Q load visible (kt=0)

        // load K tile hi/lo and VT tile
        #pragma unroll
        for (int i = 0; i < 4; i++) {
            int f = tid + i * 256;
            int row = f >> 3, c8 = (f & 7) * 8;
            size_t src = qkbase + (size_t)(kt * 128 + row) * DHEAD + c8;
            *(uint4*)&Kh[row * QS + c8] = *(const uint4*)(g_khi + src);
            *(uint4*)&Kl[row * QS + c8] = *(const uint4*)(g_klo + src);
        }
        #pragma unroll
        for (int i = 0; i < 4; i++) {
            int f = tid + i * 256;
            int row = f >> 4, c8 = (f & 15) * 8;
            *(uint4*)&Vt[row * PS + c8] =
                *(const uint4*)(g_vT16 + ((size_t)bh * DHEAD + row) * NSEQ + kt * 128 + c8);
        }
        __syncthreads();

        // S = Q K^T : 3 segments (hi*hi, lo*hi, hi*lo)
        float s[4][4][4];
        #pragma unroll
        for (int mt = 0; mt < 4; mt++)
            #pragma unroll
            for (int nt = 0; nt < 4; nt++)
                #pragma unroll
                for (int r = 0; r < 4; r++) s[mt][nt][r] = 0.0f;

        #pragma unroll
        for (int seg = 0; seg < 3; seg++) {
            const __nv_bfloat16* Aop = (seg == 1) ? Ql : Qh;
            const __nv_bfloat16* Bop = (seg == 2) ? Kl : Kh;
            #pragma unroll
            for (int ks = 0; ks < 4; ks++) {
                const int kc = ks * 16;
                uint32_t a[4][4], b[4][2];
                #pragma unroll
                for (int mt = 0; mt < 4; mt++) {
                    int r0 = wm * 64 + mt * 16;
                    a[mt][0] = *(const uint32_t*)&Aop[(r0 + g)     * QS + kc + tg * 2];
                    a[mt][1] = *(const uint32_t*)&Aop[(r0 + g + 8) * QS + kc + tg * 2];
                    a[mt][2] = *(const uint32_t*)&Aop[(r0 + g)     * QS + kc + tg * 2 + 8];
                    a[mt][3] = *(const uint32_t*)&Aop[(r0 + g + 8) * QS + kc + tg * 2 + 8];
                }
                #pragma unroll
                for (int nt = 0; nt < 4; nt++) {
                    int n0 = wn * 32 + nt * 8;
                    b[nt][0] = *(const uint32_t*)&Bop[(n0 + g) * QS + kc + tg * 2];
                    b[nt][1] = *(const uint32_t*)&Bop[(n0 + g) * QS + kc + tg * 2 + 8];
                }
                #pragma unroll
                for (int mt = 0; mt < 4; mt++)
                    #pragma unroll
                    for (int nt = 0; nt < 4; nt++)
                        mma16816(s[mt][nt], a[mt], b[nt]);
            }
        }

        // partial row max over this warp's 32 cols, two-level reduce
        #pragma unroll
        for (int mt = 0; mt < 4; mt++) {
            float mx0 = -1e30f, mx1 = -1e30f;
            #pragma unroll
            for (int nt = 0; nt < 4; nt++) {
                mx0 = fmaxf(mx0, fmaxf(s[mt][nt][0], s[mt][nt][1]));
                mx1 = fmaxf(mx1, fmaxf(s[mt][nt][2], s[mt][nt][3]));
            }
            mx0 = fmaxf(mx0, __shfl_xor_sync(0xffffffffu, mx0, 1));
            mx0 = fmaxf(mx0, __shfl_xor_sync(0xffffffffu, mx0, 2));
            mx1 = fmaxf(mx1, __shfl_xor_sync(0xffffffffu, mx1, 1));
            mx1 = fmaxf(mx1, __shfl_xor_sync(0xffffffffu, mx1, 2));
            if (tg == 0) {
                int r0 = wm * 64 + mt * 16 + g;
                pmax[r0 * 4 + wn] = mx0;
                pmax[(r0 + 8) * 4 + wn] = mx1;
            }
        }
        __syncthreads();

        if (tid < 128) {
            float mo = m_row[tid];
            float mn = fmaxf(fmaxf(pmax[tid * 4 + 0], pmax[tid * 4 + 1]),
                             fmaxf(pmax[tid * 4 + 2], pmax[tid * 4 + 3]));
            mn = fmaxf(mo, mn);
            alph[tid] = __expf(mo - mn);
            m_row[tid] = mn;
        }
        __syncthreads();

        // scale O by alpha, compute P=exp(s-m) -> fp16 Ps, row sums (of rounded values)
        #pragma unroll
        for (int mt = 0; mt < 4; mt++) {
            int r0 = wm * 64 + mt * 16 + g;
            float al0 = alph[r0], al1 = alph[r0 + 8];
            #pragma unroll
            for (int nt = 0; nt < 2; nt++) {
                o[mt][nt][0] *= al0; o[mt][nt][1] *= al0;
                o[mt][nt][2] *= al1; o[mt][nt][3] *= al1;
            }
            float m0 = m_row[r0], m1 = m_row[r0 + 8];
            float s0 = 0.0f, s1 = 0.0f;
            #pragma unroll
            for (int nt = 0; nt < 4; nt++) {
                float p0 = __expf(s[mt][nt][0] - m0);
                float p1 = __expf(s[mt][nt][1] - m0);
                float p2 = __expf(s[mt][nt][2] - m1);
                float p3 = __expf(s[mt][nt][3] - m1);
                __half2 h01 = __floats2half2_rn(p0, p1);
                __half2 h23 = __floats2half2_rn(p2, p3);
                int col = wn * 32 + nt * 8 + tg * 2;
                *(__half2*)&Pp[r0 * PS + col]       = h01;
                *(__half2*)&Pp[(r0 + 8) * PS + col] = h23;
                s0 += __low2float(h01) + __high2float(h01);
                s1 += __low2float(h23) + __high2float(h23);
            }
            s0 += __shfl_xor_sync(0xffffffffu, s0, 1);
            s0 += __shfl_xor_sync(0xffffffffu, s0, 2);
            s1 += __shfl_xor_sync(0xffffffffu, s1, 1);
            s1 += __shfl_xor_sync(0xffffffffu, s1, 2);
            if (tg == 0) {
                psum[r0 * 4 + wn] = s0;
                psum[(r0 + 8) * 4 + wn] = s1;
            }
        }
        __syncthreads();

        if (tid < 128) {
            l_row[tid] = l_row[tid] * alph[tid] +
                (psum[tid * 4 + 0] + psum[tid * 4 + 1] + psum[tid * 4 + 2] + psum[tid * 4 + 3]);
        }

        // O += P @ V  (fp16 MMA; A=Ps [q][key], B=Vt [d][key] col-major)
        #pragma unroll
        for (int ks = 0; ks < 8; ks++) {
            const int kc = ks * 16;
            uint32_t a[4][4], b[2][2];
            #pragma unroll
            for (int mt = 0; mt < 4; mt++) {
                int r0 = wm * 64 + mt * 16;
                a[mt][0] = *(const uint32_t*)&Pp[(r0 + g)     * PS + kc + tg * 2];
                a[mt][1] = *(const uint32_t*)&Pp[(r0 + g + 8) * PS + kc + tg * 2];
                a[mt][2] = *(const uint32_t*)&Pp[(r0 + g)     * PS + kc + tg * 2 + 8];
                a[mt][3] = *(const uint32_t*)&Pp[(r0 + g + 8) * PS + kc + tg * 2 + 8];
            }
            #pragma unroll
            for (int nt = 0; nt < 2; nt++) {
                int n0 = wn * 16 + nt * 8;
                b[nt][0] = *(const uint32_t*)&Vt[(n0 + g) * PS + kc + tg * 2];
                b[nt][1] = *(const uint32_t*)&Vt[(n0 + g) * PS + kc + tg * 2 + 8];
            }
            #pragma unroll
            for (int mt = 0; mt < 4; mt++)
                #pragma unroll
                for (int nt = 0; nt < 2; nt++)
                    mma16816h(o[mt][nt], a[mt], b[nt]);
        }
    }

    __syncthreads();

    // epilogue: O /= l, split to bf16 hi/lo at [b][n][h*64+d]
    const int b_ = bh >> 4;
    const int h  = bh & 15;
    #pragma unroll
    for (int mt = 0; mt < 4; mt++) {
        int r0 = wm * 64 + mt * 16 + g;
        float inv0 = 1.0f / l_row[r0];
        float inv1 = 1.0f / l_row[r0 + 8];
        #pragma unroll
        for (int nt = 0; nt < 2; nt++) {
            int d = wn * 16 + nt * 8 + tg * 2;
            #pragma unroll
            for (int rr = 0; rr < 2; rr++) {
                int row = r0 + rr * 8;
                float inv = rr ? inv1 : inv0;
                float v0 = o[mt][nt][2 * rr] * inv;
                float v1 = o[mt][nt][2 * rr + 1] * inv;
                __nv_bfloat16 h0, l0, h1, l1;
                split2(v0, h0, l0); split2(v1, h1, l1);
                size_t base = (size_t)(b_ * NSEQ + qt * 128 + row) * INNER + h * DHEAD + d;
                *(__nv_bfloat162*)(g_ahi + base) = __nv_bfloat162(h0, h1);
                *(__nv_bfloat162*)(g_alo + base) = __nv_bfloat162(l0, l1);
            }
        }
    }
}

// ============================ launch ============================
extern "C" void kernel_launch(void* const* d_in, const int* in_sizes, int n_in,
                              void* d_out, int out_size)
{
    const float* x     = (const float*)d_in[0];
    const float* w_qkv = (const float*)d_in[1];
    const float* w_out = (const float*)d_in[2];
    const float* b_out = (const float*)d_in[3];
    float* out = (float*)d_out;

    cudaFuncSetAttribute(attn_mma_kernel, cudaFuncAttributeMaxDynamicSharedMemorySize, SM_ATTN);

    split_x_kernel<<<MTOK * KDIM / 4 / 256, 256>>>(x);
    transpose_split_kernel<0><<<dim3(NQKV / 32, KDIM / 32), 256>>>(w_qkv);
    transpose_split_kernel<1><<<dim3(INNER / 32, KDIM / 32), 256>>>(w_out);

    mma_gemm_kernel<0><<<dim3(NQKV / 128, MTOK / 128), 256>>>(nullptr, nullptr);

    rope_split_kernel<<<(NB * HEADS * NSEQ * 32) / 256, 256>>>();
    v_prep_kernel<<<dim3(NSEQ / 32, DHEAD / 32, NB * HEADS), 256>>>();

    attn_mma_kernel<<<dim3(NSEQ / 128, NB * HEADS), 256, SM_ATTN>>>();

    mma_gemm_kernel<1><<<dim3(INNER / 128, MTOK / 128), 256>>>(b_out, out);
}